// round 12
// baseline (speedup 1.0000x reference)
#include <cuda_runtime.h>
#include <cuda_bf16.h>
#include <cstdint>
#include <math.h>

// ---------------------------------------------------------------------------
// Problem constants
// ---------------------------------------------------------------------------
#define HID   2048
#define NHEAD 32
#define HDIM  64
#define DFF   8192
#define SEQ   1024
#define BATCH 2
#define NTOK  (BATCH * SEQ)          // 2048 tokens

// ---------------------------------------------------------------------------
// Scratch (device globals; no allocations allowed)
// ---------------------------------------------------------------------------
__device__ float g_xln [NTOK * HID];
__device__ float g_q   [NTOK * HID];
__device__ float g_k   [NTOK * HID];
__device__ float g_v   [NTOK * HID];
__device__ float g_ctx [NTOK * HID];
__device__ float g_h   [NTOK * HID];
__device__ float g_y   [NTOK * HID];
__device__ float g_gate[(size_t)NTOK * DFF];
__device__ float g_up  [(size_t)NTOK * DFF];
// tf32-rounded copies of GEMM B-operands (weights) and memory activation
__device__ float g_memr[NTOK * HID];
__device__ float g_wq  [HID * HID];
__device__ float g_wk  [HID * HID];
__device__ float g_wv  [HID * HID];
__device__ float g_wo  [HID * HID];
__device__ float g_gw  [(size_t)DFF * HID];
__device__ float g_uw  [(size_t)DFF * HID];
__device__ float g_dw  [(size_t)HID * DFF];

// ---------------------------------------------------------------------------
// Helpers
// ---------------------------------------------------------------------------
__device__ __forceinline__ uint32_t smem_u32(const void* p) {
    uint32_t a;
    asm("{ .reg .u64 t; cvta.to.shared.u64 t, %1; cvt.u32.u64 %0, t; }"
        : "=r"(a) : "l"(p));
    return a;
}

__device__ __forceinline__ float rtf32(float x) {
    float r;
    asm("cvt.rna.tf32.f32 %0, %1;" : "=f"(r) : "f"(x));
    return r;
}

__device__ __forceinline__ void cp16(uint32_t s, const void* g) {
    asm volatile("cp.async.cg.shared.global [%0], [%1], 16;" :: "r"(s), "l"(g));
}
#define CP_COMMIT() asm volatile("cp.async.commit_group;" ::: "memory")
#define CP_WAIT2()  asm volatile("cp.async.wait_group 2;" ::: "memory")

// m16n8k8 tf32 tensor-core mma (family-target PTX, sm_80+)
__device__ __forceinline__ void mma_tf32(float* c, const uint32_t* a, const uint32_t* b) {
    asm volatile(
        "mma.sync.aligned.m16n8k8.row.col.f32.tf32.tf32.f32 "
        "{%0,%1,%2,%3}, {%4,%5,%6,%7}, {%8,%9}, {%0,%1,%2,%3};"
        : "+f"(c[0]), "+f"(c[1]), "+f"(c[2]), "+f"(c[3])
        : "r"(a[0]), "r"(a[1]), "r"(a[2]), "r"(a[3]), "r"(b[0]), "r"(b[1]));
}

// ---------------------------------------------------------------------------
// Elementwise tf32 rounding pass (weights + memory operand)
// ---------------------------------------------------------------------------
__global__ void round_tf32_k(const float* __restrict__ x, float* __restrict__ y, int n4)
{
    const int i = blockIdx.x * blockDim.x + threadIdx.x;
    if (i >= n4) return;
    float4 v = ((const float4*)x)[i];
    v.x = rtf32(v.x); v.y = rtf32(v.y); v.z = rtf32(v.z); v.w = rtf32(v.w);
    ((float4*)y)[i] = v;
}

// ---------------------------------------------------------------------------
// LayerNorm: one block per row; output rounded to tf32 (feeds GEMM A-operand)
// ---------------------------------------------------------------------------
__global__ __launch_bounds__(256) void layernorm_k(
    const float* __restrict__ X, const float* __restrict__ w,
    const float* __restrict__ b, float* __restrict__ Y)
{
    const int row = blockIdx.x;
    const float* x = X + (size_t)row * HID;
    float sum = 0.f, sq = 0.f;
    for (int c = threadIdx.x * 4; c < HID; c += 256 * 4) {
        float4 v = *(const float4*)(x + c);
        sum += v.x + v.y + v.z + v.w;
        sq  += v.x * v.x + v.y * v.y + v.z * v.z + v.w * v.w;
    }
    __shared__ float s1[8], s2[8];
    #pragma unroll
    for (int o = 16; o > 0; o >>= 1) {
        sum += __shfl_xor_sync(0xffffffffu, sum, o);
        sq  += __shfl_xor_sync(0xffffffffu, sq, o);
    }
    if ((threadIdx.x & 31) == 0) { s1[threadIdx.x >> 5] = sum; s2[threadIdx.x >> 5] = sq; }
    __syncthreads();
    if (threadIdx.x < 32) {
        sum = (threadIdx.x < 8) ? s1[threadIdx.x] : 0.f;
        sq  = (threadIdx.x < 8) ? s2[threadIdx.x] : 0.f;
        #pragma unroll
        for (int o = 4; o > 0; o >>= 1) {
            sum += __shfl_xor_sync(0xffffffffu, sum, o);
            sq  += __shfl_xor_sync(0xffffffffu, sq, o);
        }
        if (threadIdx.x == 0) { s1[0] = sum; s2[0] = sq; }
    }
    __syncthreads();
    const float mean = s1[0] * (1.f / HID);
    const float var  = s2[0] * (1.f / HID) - mean * mean;
    const float rstd = rsqrtf(var + 1e-5f);
    float* y = Y + (size_t)row * HID;
    for (int c = threadIdx.x * 4; c < HID; c += 256 * 4) {
        float4 v  = *(const float4*)(x + c);
        float4 wv = *(const float4*)(w + c);
        float4 bv = *(const float4*)(b + c);
        float4 o;
        o.x = rtf32((v.x - mean) * rstd * wv.x + bv.x);
        o.y = rtf32((v.y - mean) * rstd * wv.y + bv.y);
        o.z = rtf32((v.z - mean) * rstd * wv.z + bv.z);
        o.w = rtf32((v.w - mean) * rstd * wv.w + bv.w);
        *(float4*)(y + c) = o;
    }
}

// ---------------------------------------------------------------------------
// TF32 tensor-core NT GEMM via mma.sync:  C[M,N] = A[M,K]*B[N,K]^T (+ Cin)
// CTA 128x256, BK=16, 256 threads (8 warps = 2x4), warp tile 64x64.
// 4-stage cp.async pipeline (wait_group 2). smem [row][20] pad, conflict-free.
// M%128==0, N%256==0, K%16==0 for all calls here.
// ---------------------------------------------------------------------------
#define GM 128
#define GN 256
#define GK 16
#define LDS_K 20                          // GK + 4 pad
#define A_STG (GM * LDS_K)                // 2560 floats
#define B_STG (GN * LDS_K)                // 5120 floats
#define NSTAGE 4
#define GEMM_SMEM (NSTAGE * (A_STG + B_STG) * 4)   // 122880 bytes

__device__ __forceinline__ void load_stage(
    int tid, const float* Ag, const float* Bg, int K, int k0,
    uint32_t sA, uint32_t sB)
{
    #pragma unroll
    for (int t = 0; t < 2; t++) {
        const int idx = tid + t * 256;
        const int row = idx >> 2, c4 = idx & 3;
        cp16(sA + (uint32_t)(row * LDS_K + c4 * 4) * 4, Ag + (size_t)row * K + k0 + c4 * 4);
    }
    #pragma unroll
    for (int t = 0; t < 4; t++) {
        const int idx = tid + t * 256;
        const int row = idx >> 2, c4 = idx & 3;
        cp16(sB + (uint32_t)(row * LDS_K + c4 * 4) * 4, Bg + (size_t)row * K + k0 + c4 * 4);
    }
}

__global__ __launch_bounds__(256, 1) void gemm_mma(
    const float* __restrict__ A, const float* __restrict__ B,
    const float* __restrict__ Cin, float* __restrict__ C,
    int M, int N, int K)
{
    extern __shared__ float dsm[];
    float* smA = dsm;                          // [NSTAGE][A_STG]
    float* smB = dsm + NSTAGE * A_STG;         // [NSTAGE][B_STG]

    const int tid  = threadIdx.x;
    const int wid  = tid >> 5;
    const int lane = tid & 31;
    const int wm   = wid & 1;          // warp m index (0..1) -> 64 rows
    const int wn   = wid >> 1;         // warp n index (0..3) -> 64 cols
    const int m0   = blockIdx.y * GM;
    const int n0   = blockIdx.x * GN;

    const float* Ag = A + (size_t)m0 * K;
    const float* Bg = B + (size_t)n0 * K;

    const uint32_t sAu = smem_u32(smA);
    const uint32_t sBu = smem_u32(smB);

    float acc[4][8][4] = {};   // [mf][nf][reg]

    const int S = K / GK;

    // prologue: stages 0..2 in flight
    #pragma unroll
    for (int p = 0; p < 3; p++) {
        load_stage(tid, Ag, Bg, K, p * GK,
                   sAu + (uint32_t)(p * A_STG) * 4, sBu + (uint32_t)(p * B_STG) * 4);
        CP_COMMIT();
    }

    const int lr = lane >> 2;          // 0..7
    const int lc = lane & 3;           // 0..3

    for (int s = 0; s < S; s++) {
        const int b = s & (NSTAGE - 1);
        CP_WAIT2();                    // stage s landed (2 younger may be in flight)
        __syncthreads();

        // issue stage s+3 into buffer (s+3)%4 == (s-1)%4 (consumed, all past sync)
        if (s + 3 < S) {
            const int nb = (s + 3) & (NSTAGE - 1);
            load_stage(tid, Ag, Bg, K, (s + 3) * GK,
                       sAu + (uint32_t)(nb * A_STG) * 4, sBu + (uint32_t)(nb * B_STG) * 4);
        }
        CP_COMMIT();                   // always commit (empty group ok)

        const float* As = smA + b * A_STG;
        const float* Bs = smB + b * B_STG;

        #pragma unroll
        for (int ks = 0; ks < 2; ks++) {
            const int k0 = ks * 8;
            uint32_t af[4][4];
            #pragma unroll
            for (int mf = 0; mf < 4; mf++) {
                const float* ap = As + (wm * 64 + mf * 16 + lr) * LDS_K + k0 + lc;
                af[mf][0] = __float_as_uint(ap[0]);
                af[mf][1] = __float_as_uint(ap[8 * LDS_K]);
                af[mf][2] = __float_as_uint(ap[4]);
                af[mf][3] = __float_as_uint(ap[8 * LDS_K + 4]);
            }
            uint32_t bf[8][2];
            #pragma unroll
            for (int nf = 0; nf < 8; nf++) {
                const float* bp = Bs + (wn * 64 + nf * 8 + lr) * LDS_K + k0 + lc;
                bf[nf][0] = __float_as_uint(bp[0]);
                bf[nf][1] = __float_as_uint(bp[4]);
            }
            #pragma unroll
            for (int mf = 0; mf < 4; mf++)
                #pragma unroll
                for (int nf = 0; nf < 8; nf++)
                    mma_tf32(acc[mf][nf], af[mf], bf[nf]);
        }
        __syncthreads();
    }

    // epilogue: frag (mf,nf): rows m0+wm*64+mf*16+{lr,lr+8}, cols n0+wn*64+nf*8+2*lc
    #pragma unroll
    for (int mf = 0; mf < 4; mf++) {
        const int r0 = m0 + wm * 64 + mf * 16 + lr;
        #pragma unroll
        for (int nf = 0; nf < 8; nf++) {
            const int c0 = n0 + wn * 64 + nf * 8 + 2 * lc;
            float2 v0 = make_float2(acc[mf][nf][0], acc[mf][nf][1]);
            float2 v1 = make_float2(acc[mf][nf][2], acc[mf][nf][3]);
            if (Cin) {
                const float2 p0 = *(const float2*)(Cin + (size_t)r0 * N + c0);
                const float2 p1 = *(const float2*)(Cin + (size_t)(r0 + 8) * N + c0);
                v0.x += p0.x; v0.y += p0.y;
                v1.x += p1.x; v1.y += p1.y;
            }
            *(float2*)(C + (size_t)r0 * N + c0)       = v0;
            *(float2*)(C + (size_t)(r0 + 8) * N + c0) = v1;
        }
    }
}

// ---------------------------------------------------------------------------
// RoPE in-place on q and k (first 16 dims per head).
// ---------------------------------------------------------------------------
__global__ void rope_k(float* __restrict__ q, float* __restrict__ k,
                       const int* __restrict__ pos_ids)
{
    const int idx = blockIdx.x * blockDim.x + threadIdx.x;
    const int total = NTOK * NHEAD * 8;
    if (idx >= total) return;
    const int d   = idx & 7;
    const int h   = (idx >> 3) & (NHEAD - 1);
    const int tkn = idx >> 8;
    const float pos = (float)pos_ids[tkn];
    const float inv = powf(10000.f, -(float)d * 0.125f);
    float s, c;
    sincosf(pos * inv, &s, &c);
    const size_t base = (size_t)tkn * HID + h * HDIM;
    {
        const float x0 = q[base + d], x1 = q[base + d + 8];
        q[base + d]     = x0 * c - x1 * s;
        q[base + d + 8] = x1 * c + x0 * s;
    }
    {
        const float x0 = k[base + d], x1 = k[base + d + 8];
        k[base + d]     = x0 * c - x1 * s;
        k[base + d + 8] = x1 * c + x0 * s;
    }
}

// ---------------------------------------------------------------------------
// Flash attention (fp32) — output rounded to tf32 (feeds Wo GEMM)
// ---------------------------------------------------------------------------
__global__ __launch_bounds__(256) void attn_k(
    const float* __restrict__ Q, const float* __restrict__ K,
    const float* __restrict__ V, const float* __restrict__ mask,
    float* __restrict__ O)
{
    __shared__ float sm[3 * 64 * 64];
    float* Qs = sm;
    float* Ks = sm + 4096;
    float* Vs = sm + 8192;
    float* Ps = Ks;

    const int qt = blockIdx.x, h = blockIdx.y, b = blockIdx.z;
    const int tid  = threadIdx.x;
    const int r    = tid >> 2;
    const int part = tid & 3;
    const int d0   = part * 16;

    const size_t qbase = ((size_t)(b * SEQ + qt * 64) * HID) + h * HDIM;

    for (int i = tid; i < 64 * 16; i += 256) {
        const int row = i >> 4, c4 = (i & 15) * 4;
        float4 v = *(const float4*)(Q + qbase + (size_t)row * HID + c4);
        v.x *= 0.125f; v.y *= 0.125f; v.z *= 0.125f; v.w *= 0.125f;
        *(float4*)(Qs + row * 64 + c4) = v;
    }

    float acc[16] = {};
    float mrun = -1e30f, lrun = 0.f;
    const float* maskrow = mask + (size_t)b * SEQ * SEQ + (size_t)(qt * 64 + r) * SEQ;

    for (int t = 0; t < SEQ / 64; t++) {
        __syncthreads();
        const size_t kvb = ((size_t)(b * SEQ + t * 64) * HID) + h * HDIM;
        for (int i = tid; i < 64 * 16; i += 256) {
            const int row = i >> 4, c4 = (i & 15) * 4;
            *(float4*)(Ks + row * 64 + c4) = *(const float4*)(K + kvb + (size_t)row * HID + c4);
            *(float4*)(Vs + row * 64 + c4) = *(const float4*)(V + kvb + (size_t)row * HID + c4);
        }
        __syncthreads();

        float sc[16];
        const float4* qrow = (const float4*)(Qs + r * 64);
        #pragma unroll
        for (int jj = 0; jj < 16; jj++) {
            const int j = d0 + jj;
            const float4* krow = (const float4*)(Ks + j * 64);
            float s = 0.f;
            #pragma unroll
            for (int d4 = 0; d4 < 16; d4++) {
                const float4 a = qrow[d4], bb = krow[d4];
                s += a.x * bb.x + a.y * bb.y + a.z * bb.z + a.w * bb.w;
            }
            sc[jj] = s + maskrow[t * 64 + j];
        }

        float mt = sc[0];
        #pragma unroll
        for (int jj = 1; jj < 16; jj++) mt = fmaxf(mt, sc[jj]);
        mt = fmaxf(mt, __shfl_xor_sync(0xffffffffu, mt, 1));
        mt = fmaxf(mt, __shfl_xor_sync(0xffffffffu, mt, 2));
        const float mnew  = fmaxf(mrun, mt);
        const float scale = __expf(mrun - mnew);

        float lsum = 0.f;
        #pragma unroll
        for (int jj = 0; jj < 16; jj++) { sc[jj] = __expf(sc[jj] - mnew); lsum += sc[jj]; }
        lsum += __shfl_xor_sync(0xffffffffu, lsum, 1);
        lsum += __shfl_xor_sync(0xffffffffu, lsum, 2);
        lrun = lrun * scale + lsum;
        mrun = mnew;
        #pragma unroll
        for (int dd = 0; dd < 16; dd++) acc[dd] *= scale;

        __syncthreads();
        #pragma unroll
        for (int jj = 0; jj < 16; jj++) Ps[r * 64 + d0 + jj] = sc[jj];
        __syncthreads();

        #pragma unroll
        for (int j = 0; j < 64; j++) {
            const float pv = Ps[r * 64 + j];
            const float4* vrow = (const float4*)(Vs + j * 64 + d0);
            #pragma unroll
            for (int q4 = 0; q4 < 4; q4++) {
                const float4 v = vrow[q4];
                acc[q4 * 4 + 0] += pv * v.x;
                acc[q4 * 4 + 1] += pv * v.y;
                acc[q4 * 4 + 2] += pv * v.z;
                acc[q4 * 4 + 3] += pv * v.w;
            }
        }
    }

    const float inv_l = 1.f / lrun;
    float* orow = O + qbase + (size_t)r * HID + d0;
    #pragma unroll
    for (int dd = 0; dd < 16; dd += 4) {
        float4 v = make_float4(rtf32(acc[dd] * inv_l),     rtf32(acc[dd + 1] * inv_l),
                               rtf32(acc[dd + 2] * inv_l), rtf32(acc[dd + 3] * inv_l));
        *(float4*)(orow + dd) = v;
    }
}

// ---------------------------------------------------------------------------
// act = silu(gate) * up (in place into gate), rounded to tf32
// ---------------------------------------------------------------------------
__global__ void silu_mul_k(float* __restrict__ g, const float* __restrict__ u, int n4)
{
    const int i = blockIdx.x * blockDim.x + threadIdx.x;
    if (i >= n4) return;
    float4 gv = *(float4*)(g + (size_t)i * 4);
    const float4 uv = *(const float4*)(u + (size_t)i * 4);
    gv.x = rtf32(gv.x / (1.f + __expf(-gv.x)) * uv.x);
    gv.y = rtf32(gv.y / (1.f + __expf(-gv.y)) * uv.y);
    gv.z = rtf32(gv.z / (1.f + __expf(-gv.z)) * uv.z);
    gv.w = rtf32(gv.w / (1.f + __expf(-gv.w)) * uv.w);
    *(float4*)(g + (size_t)i * 4) = gv;
}

// ---------------------------------------------------------------------------
// Orchestration
// ---------------------------------------------------------------------------
static inline void round_pass(const float* src, float* dst, size_t n)
{
    const int n4 = (int)(n / 4);
    round_tf32_k<<<(n4 + 255) / 256, 256>>>(src, dst, n4);
}

extern "C" void kernel_launch(void* const* d_in, const int* in_sizes, int n_in,
                              void* d_out, int out_size)
{
    const float* hid   = (const float*)d_in[0];
    const float* mem   = (const float*)d_in[1];
    const float* mask  = (const float*)d_in[2];
    const int*   pos   = (const int*)  d_in[3];
    const float* Wq    = (const float*)d_in[4];
    const float* Wk    = (const float*)d_in[5];
    const float* Wv    = (const float*)d_in[6];
    const float* Wo    = (const float*)d_in[7];
    const float* ln1w  = (const float*)d_in[8];
    const float* ln1b  = (const float*)d_in[9];
    const float* ln2w  = (const float*)d_in[10];
    const float* ln2b  = (const float*)d_in[11];
    const float* gatew = (const float*)d_in[12];
    const float* upw   = (const float*)d_in[13];
    const float* downw = (const float*)d_in[14];
    float* out = (float*)d_out;

    float *xln, *q, *k, *v, *ctx, *h, *y, *gg, *uu;
    float *memr, *wq, *wk, *wv, *wo, *gw, *uw, *dw;
    cudaGetSymbolAddress((void**)&xln, g_xln);
    cudaGetSymbolAddress((void**)&q,   g_q);
    cudaGetSymbolAddress((void**)&k,   g_k);
    cudaGetSymbolAddress((void**)&v,   g_v);
    cudaGetSymbolAddress((void**)&ctx, g_ctx);
    cudaGetSymbolAddress((void**)&h,   g_h);
    cudaGetSymbolAddress((void**)&y,   g_y);
    cudaGetSymbolAddress((void**)&gg,  g_gate);
    cudaGetSymbolAddress((void**)&uu,  g_up);
    cudaGetSymbolAddress((void**)&memr, g_memr);
    cudaGetSymbolAddress((void**)&wq,  g_wq);
    cudaGetSymbolAddress((void**)&wk,  g_wk);
    cudaGetSymbolAddress((void**)&wv,  g_wv);
    cudaGetSymbolAddress((void**)&wo,  g_wo);
    cudaGetSymbolAddress((void**)&gw,  g_gw);
    cudaGetSymbolAddress((void**)&uw,  g_uw);
    cudaGetSymbolAddress((void**)&dw,  g_dw);

    // dynamic smem opt-in (immediate host-side call; not a stream op)
    cudaFuncSetAttribute(gemm_mma, cudaFuncAttributeMaxDynamicSharedMemorySize, GEMM_SMEM);

    // tf32-round GEMM B operands (weights) + memory activation
    round_pass(Wq, wq, (size_t)HID * HID);
    round_pass(Wk, wk, (size_t)HID * HID);
    round_pass(Wv, wv, (size_t)HID * HID);
    round_pass(Wo, wo, (size_t)HID * HID);
    round_pass(gatew, gw, (size_t)DFF * HID);
    round_pass(upw,   uw, (size_t)DFF * HID);
    round_pass(downw, dw, (size_t)HID * DFF);
    round_pass(mem, memr, (size_t)NTOK * HID);

    // 1. ln1 (tf32-rounded output)
    layernorm_k<<<NTOK, 256>>>(hid, ln1w, ln1b, xln);

    // 2-4. Q/K/V projections (tensor-core tf32 GEMMs)
    dim3 gsq(HID / GN, NTOK / GM);
    gemm_mma<<<gsq, 256, GEMM_SMEM>>>(xln,  wq, nullptr, q, NTOK, HID, HID);
    gemm_mma<<<gsq, 256, GEMM_SMEM>>>(memr, wk, nullptr, k, NTOK, HID, HID);
    gemm_mma<<<gsq, 256, GEMM_SMEM>>>(memr, wv, nullptr, v, NTOK, HID, HID);

    // 5. RoPE (in place)
    const int rope_threads = NTOK * NHEAD * 8;
    rope_k<<<(rope_threads + 255) / 256, 256>>>(q, k, pos);

    // 6. Attention -> ctx (tf32-rounded)
    dim3 ga(SEQ / 64, NHEAD, BATCH);
    attn_k<<<ga, 256>>>(q, k, v, mask, ctx);

    // 7. O projection + residual
    gemm_mma<<<gsq, 256, GEMM_SMEM>>>(ctx, wo, hid, h, NTOK, HID, HID);

    // 8. ln2 (rounded)
    layernorm_k<<<NTOK, 256>>>(h, ln2w, ln2b, y);

    // 9-10. gate / up
    dim3 gff(DFF / GN, NTOK / GM);
    gemm_mma<<<gff, 256, GEMM_SMEM>>>(y, gw, nullptr, gg, NTOK, DFF, HID);
    gemm_mma<<<gff, 256, GEMM_SMEM>>>(y, uw, nullptr, uu, NTOK, DFF, HID);

    // 11. silu(gate) * up  (in place into gg, rounded)
    const int n4 = (NTOK * DFF) / 4;
    silu_mul_k<<<(n4 + 255) / 256, 256>>>(gg, uu, n4);

    // 12. down projection + residual -> out
    gemm_mma<<<gsq, 256, GEMM_SMEM>>>(gg, dw, h, out, NTOK, HID, DFF);
}

// round 14
// speedup vs baseline: 1.2621x; 1.2621x over previous
#include <cuda_runtime.h>
#include <cuda_fp16.h>
#include <cstdint>
#include <math.h>

// ---------------------------------------------------------------------------
// Problem constants
// ---------------------------------------------------------------------------
#define HID   2048
#define NHEAD 32
#define HDIM  64
#define DFF   8192
#define SEQ   1024
#define BATCH 2
#define NTOK  (BATCH * SEQ)          // 2048 tokens

// ---------------------------------------------------------------------------
// Scratch (device globals; no allocations allowed)
// ---------------------------------------------------------------------------
__device__ float  g_q   [NTOK * HID];
__device__ float  g_k   [NTOK * HID];
__device__ float  g_v   [NTOK * HID];
__device__ float  g_h   [NTOK * HID];
__device__ float  g_gate[(size_t)NTOK * DFF];
__device__ float  g_up  [(size_t)NTOK * DFF];
// half activations (GEMM A-operands)
__device__ __half g_xln_h[NTOK * HID];
__device__ __half g_mem_h[NTOK * HID];
__device__ __half g_ctx_h[NTOK * HID];
__device__ __half g_y_h  [NTOK * HID];
__device__ __half g_act_h[(size_t)NTOK * DFF];
// half weights (GEMM B-operands)
__device__ __half g_wq [HID * HID];
__device__ __half g_wk [HID * HID];
__device__ __half g_wv [HID * HID];
__device__ __half g_wo [HID * HID];
__device__ __half g_gw [(size_t)DFF * HID];
__device__ __half g_uw [(size_t)DFF * HID];
__device__ __half g_dw [(size_t)HID * DFF];

// ---------------------------------------------------------------------------
// Helpers
// ---------------------------------------------------------------------------
__device__ __forceinline__ uint32_t smem_u32(const void* p) {
    uint32_t a;
    asm("{ .reg .u64 t; cvta.to.shared.u64 t, %1; cvt.u32.u64 %0, t; }"
        : "=r"(a) : "l"(p));
    return a;
}

__device__ __forceinline__ void cp16(uint32_t s, const void* g) {
    asm volatile("cp.async.cg.shared.global [%0], [%1], 16;" :: "r"(s), "l"(g));
}
#define CP_COMMIT() asm volatile("cp.async.commit_group;" ::: "memory")
#define CP_WAIT2()  asm volatile("cp.async.wait_group 2;" ::: "memory")

// fp16 tensor-core mma, fp32 accumulate (sm_80+ PTX, family-target safe)
__device__ __forceinline__ void mma_f16(float* c, const uint32_t* a, const uint32_t* b) {
    asm volatile(
        "mma.sync.aligned.m16n8k16.row.col.f32.f16.f16.f32 "
        "{%0,%1,%2,%3}, {%4,%5,%6,%7}, {%8,%9}, {%0,%1,%2,%3};"
        : "+f"(c[0]), "+f"(c[1]), "+f"(c[2]), "+f"(c[3])
        : "r"(a[0]), "r"(a[1]), "r"(a[2]), "r"(a[3]), "r"(b[0]), "r"(b[1]));
}

__device__ __forceinline__ void ldsm_x4(uint32_t* r, uint32_t addr) {
    asm volatile("ldmatrix.sync.aligned.m8n8.x4.shared.b16 {%0,%1,%2,%3}, [%4];"
        : "=r"(r[0]), "=r"(r[1]), "=r"(r[2]), "=r"(r[3]) : "r"(addr));
}

// ---------------------------------------------------------------------------
// f32 -> f16 conversion pass (weights + memory operand); rn = unbiased
// ---------------------------------------------------------------------------
__global__ void to_half_k(const float* __restrict__ x, __half* __restrict__ y, int n4)
{
    const int i = blockIdx.x * blockDim.x + threadIdx.x;
    if (i >= n4) return;
    const float4 v = ((const float4*)x)[i];
    __half2 h0 = __floats2half2_rn(v.x, v.y);
    __half2 h1 = __floats2half2_rn(v.z, v.w);
    ((uint2*)y)[i] = make_uint2(*(uint32_t*)&h0, *(uint32_t*)&h1);
}

// ---------------------------------------------------------------------------
// LayerNorm: one block per row; writes half (feeds GEMM A-operand)
// ---------------------------------------------------------------------------
__global__ __launch_bounds__(256) void layernorm_k(
    const float* __restrict__ X, const float* __restrict__ w,
    const float* __restrict__ b, __half* __restrict__ Y)
{
    const int row = blockIdx.x;
    const float* x = X + (size_t)row * HID;
    float sum = 0.f, sq = 0.f;
    for (int c = threadIdx.x * 4; c < HID; c += 256 * 4) {
        float4 v = *(const float4*)(x + c);
        sum += v.x + v.y + v.z + v.w;
        sq  += v.x * v.x + v.y * v.y + v.z * v.z + v.w * v.w;
    }
    __shared__ float s1[8], s2[8];
    #pragma unroll
    for (int o = 16; o > 0; o >>= 1) {
        sum += __shfl_xor_sync(0xffffffffu, sum, o);
        sq  += __shfl_xor_sync(0xffffffffu, sq, o);
    }
    if ((threadIdx.x & 31) == 0) { s1[threadIdx.x >> 5] = sum; s2[threadIdx.x >> 5] = sq; }
    __syncthreads();
    if (threadIdx.x < 32) {
        sum = (threadIdx.x < 8) ? s1[threadIdx.x] : 0.f;
        sq  = (threadIdx.x < 8) ? s2[threadIdx.x] : 0.f;
        #pragma unroll
        for (int o = 4; o > 0; o >>= 1) {
            sum += __shfl_xor_sync(0xffffffffu, sum, o);
            sq  += __shfl_xor_sync(0xffffffffu, sq, o);
        }
        if (threadIdx.x == 0) { s1[0] = sum; s2[0] = sq; }
    }
    __syncthreads();
    const float mean = s1[0] * (1.f / HID);
    const float var  = s2[0] * (1.f / HID) - mean * mean;
    const float rstd = rsqrtf(var + 1e-5f);
    __half* y = Y + (size_t)row * HID;
    for (int c = threadIdx.x * 4; c < HID; c += 256 * 4) {
        float4 v  = *(const float4*)(x + c);
        float4 wv = *(const float4*)(w + c);
        float4 bv = *(const float4*)(b + c);
        __half2 h0 = __floats2half2_rn((v.x - mean) * rstd * wv.x + bv.x,
                                       (v.y - mean) * rstd * wv.y + bv.y);
        __half2 h1 = __floats2half2_rn((v.z - mean) * rstd * wv.z + bv.z,
                                       (v.w - mean) * rstd * wv.w + bv.w);
        *(uint2*)(y + c) = make_uint2(*(uint32_t*)&h0, *(uint32_t*)&h1);
    }
}

// ---------------------------------------------------------------------------
// FP16 tensor-core NT GEMM:  C[M,N] = A[M,K]*B[N,K]^T (+ Cin), fp32 accum
// CTA 128x256, BK=32 halves, 256 threads (8 warps = 2x4), warp tile 64x64.
// 4-stage cp.async pipeline, ldmatrix fragment loads.
// Row stride 40 halves (pad 8) -> conflict-free for cp.async and ldmatrix.
// ---------------------------------------------------------------------------
#define GM 128
#define GN 256
#define BKH 32                            // K halves per stage
#define LDH 40                            // row stride in halves
#define A_STG (GM * LDH)                  // halves
#define B_STG (GN * LDH)
#define NSTAGE 4
#define GEMM_SMEM (NSTAGE * (A_STG + B_STG) * 2)   // 122880 bytes

__device__ __forceinline__ void load_stage_h(
    int tid, const __half* Ag, const __half* Bg, int K, int k0,
    uint32_t sA, uint32_t sB)
{
    #pragma unroll
    for (int t = 0; t < 2; t++) {
        const int idx = tid + t * 256;
        const int row = idx >> 2, c = idx & 3;
        cp16(sA + (uint32_t)(row * LDH + c * 8) * 2, Ag + (size_t)row * K + k0 + c * 8);
    }
    #pragma unroll
    for (int t = 0; t < 4; t++) {
        const int idx = tid + t * 256;
        const int row = idx >> 2, c = idx & 3;
        cp16(sB + (uint32_t)(row * LDH + c * 8) * 2, Bg + (size_t)row * K + k0 + c * 8);
    }
}

__global__ __launch_bounds__(256, 1) void gemm_mma(
    const __half* __restrict__ A, const __half* __restrict__ B,
    const float* __restrict__ Cin, float* __restrict__ C,
    int M, int N, int K)
{
    extern __shared__ __half hsm[];
    __half* smA = hsm;                         // [NSTAGE][A_STG]
    __half* smB = hsm + NSTAGE * A_STG;        // [NSTAGE][B_STG]

    const int tid  = threadIdx.x;
    const int wid  = tid >> 5;
    const int lane = tid & 31;
    const int wm   = wid & 1;          // warp m (0..1) -> 64 rows
    const int wn   = wid >> 1;         // warp n (0..3) -> 64 cols
    const int m0   = blockIdx.y * GM;
    const int n0   = blockIdx.x * GN;

    const __half* Ag = A + (size_t)m0 * K;
    const __half* Bg = B + (size_t)n0 * K;

    const uint32_t sAu = smem_u32(smA);
    const uint32_t sBu = smem_u32(smB);

    // ldmatrix lane address components
    const int rowA = wm * 64 + (lane & 7) + 8 * ((lane >> 3) & 1);  // + mf*16
    const int kA   = 8 * (lane >> 4);
    const int rowB = wn * 64 + (lane & 7) + 8 * (lane >> 4);        // + np*16
    const int kB   = 8 * ((lane >> 3) & 1);

    float acc[4][8][4] = {};   // [mf][nf][reg]

    const int S = K / BKH;

    #pragma unroll
    for (int p = 0; p < 3; p++) {
        load_stage_h(tid, Ag, Bg, K, p * BKH,
                     sAu + (uint32_t)(p * A_STG) * 2, sBu + (uint32_t)(p * B_STG) * 2);
        CP_COMMIT();
    }

    for (int s = 0; s < S; s++) {
        const int b = s & (NSTAGE - 1);
        CP_WAIT2();
        __syncthreads();

        if (s + 3 < S) {
            const int nb = (s + 3) & (NSTAGE - 1);
            load_stage_h(tid, Ag, Bg, K, (s + 3) * BKH,
                         sAu + (uint32_t)(nb * A_STG) * 2, sBu + (uint32_t)(nb * B_STG) * 2);
        }
        CP_COMMIT();

        const uint32_t aBase = sAu + (uint32_t)(b * A_STG) * 2;
        const uint32_t bBase = sBu + (uint32_t)(b * B_STG) * 2;

        #pragma unroll
        for (int ks = 0; ks < 2; ks++) {
            const int k0 = ks * 16;
            uint32_t af[4][4];
            #pragma unroll
            for (int mf = 0; mf < 4; mf++)
                ldsm_x4(af[mf], aBase + (uint32_t)((rowA + mf * 16) * LDH + k0 + kA) * 2);
            uint32_t bf[4][4];
            #pragma unroll
            for (int np = 0; np < 4; np++)
                ldsm_x4(bf[np], bBase + (uint32_t)((rowB + np * 16) * LDH + k0 + kB) * 2);
            #pragma unroll
            for (int mf = 0; mf < 4; mf++)
                #pragma unroll
                for (int nf = 0; nf < 8; nf++)
                    mma_f16(acc[mf][nf], af[mf], bf[nf >> 1] + 2 * (nf & 1));
        }
        __syncthreads();
    }

    const int lr = lane >> 2;
    const int lc = lane & 3;
    #pragma unroll
    for (int mf = 0; mf < 4; mf++) {
        const int r0 = m0 + wm * 64 + mf * 16 + lr;
        #pragma unroll
        for (int nf = 0; nf < 8; nf++) {
            const int c0 = n0 + wn * 64 + nf * 8 + 2 * lc;
            float2 v0 = make_float2(acc[mf][nf][0], acc[mf][nf][1]);
            float2 v1 = make_float2(acc[mf][nf][2], acc[mf][nf][3]);
            if (Cin) {
                const float2 p0 = *(const float2*)(Cin + (size_t)r0 * N + c0);
                const float2 p1 = *(const float2*)(Cin + (size_t)(r0 + 8) * N + c0);
                v0.x += p0.x; v0.y += p0.y;
                v1.x += p1.x; v1.y += p1.y;
            }
            *(float2*)(C + (size_t)r0 * N + c0)       = v0;
            *(float2*)(C + (size_t)(r0 + 8) * N + c0) = v1;
        }
    }
}

// ---------------------------------------------------------------------------
// RoPE in-place on q and k (first 16 dims per head).
// ---------------------------------------------------------------------------
__global__ void rope_k(float* __restrict__ q, float* __restrict__ k,
                       const int* __restrict__ pos_ids)
{
    const int idx = blockIdx.x * blockDim.x + threadIdx.x;
    const int total = NTOK * NHEAD * 8;
    if (idx >= total) return;
    const int d   = idx & 7;
    const int h   = (idx >> 3) & (NHEAD - 1);
    const int tkn = idx >> 8;
    const float pos = (float)pos_ids[tkn];
    const float inv = powf(10000.f, -(float)d * 0.125f);
    float s, c;
    sincosf(pos * inv, &s, &c);
    const size_t base = (size_t)tkn * HID + h * HDIM;
    {
        const float x0 = q[base + d], x1 = q[base + d + 8];
        q[base + d]     = x0 * c - x1 * s;
        q[base + d + 8] = x1 * c + x0 * s;
    }
    {
        const float x0 = k[base + d], x1 = k[base + d + 8];
        k[base + d]     = x0 * c - x1 * s;
        k[base + d + 8] = x1 * c + x0 * s;
    }
}

// ---------------------------------------------------------------------------
// Flash attention (fp32 SIMT) — writes half ctx (feeds Wo GEMM)
// ---------------------------------------------------------------------------
__global__ __launch_bounds__(256) void attn_k(
    const float* __restrict__ Q, const float* __restrict__ K,
    const float* __restrict__ V, const float* __restrict__ mask,
    __half* __restrict__ O)
{
    __shared__ float sm[3 * 64 * 64];
    float* Qs = sm;
    float* Ks = sm + 4096;
    float* Vs = sm + 8192;
    float* Ps = Ks;

    const int qt = blockIdx.x, h = blockIdx.y, b = blockIdx.z;
    const int tid  = threadIdx.x;
    const int r    = tid >> 2;
    const int part = tid & 3;
    const int d0   = part * 16;

    const size_t qbase = ((size_t)(b * SEQ + qt * 64) * HID) + h * HDIM;

    for (int i = tid; i < 64 * 16; i += 256) {
        const int row = i >> 4, c4 = (i & 15) * 4;
        float4 v = *(const float4*)(Q + qbase + (size_t)row * HID + c4);
        v.x *= 0.125f; v.y *= 0.125f; v.z *= 0.125f; v.w *= 0.125f;
        *(float4*)(Qs + row * 64 + c4) = v;
    }

    float acc[16] = {};
    float mrun = -1e30f, lrun = 0.f;
    const float* maskrow = mask + (size_t)b * SEQ * SEQ + (size_t)(qt * 64 + r) * SEQ;

    for (int t = 0; t < SEQ / 64; t++) {
        __syncthreads();
        const size_t kvb = ((size_t)(b * SEQ + t * 64) * HID) + h * HDIM;
        for (int i = tid; i < 64 * 16; i += 256) {
            const int row = i >> 4, c4 = (i & 15) * 4;
            *(float4*)(Ks + row * 64 + c4) = *(const float4*)(K + kvb + (size_t)row * HID + c4);
            *(float4*)(Vs + row * 64 + c4) = *(const float4*)(V + kvb + (size_t)row * HID + c4);
        }
        __syncthreads();

        float sc[16];
        const float4* qrow = (const float4*)(Qs + r * 64);
        #pragma unroll
        for (int jj = 0; jj < 16; jj++) {
            const int j = d0 + jj;
            const float4* krow = (const float4*)(Ks + j * 64);
            float s = 0.f;
            #pragma unroll
            for (int d4 = 0; d4 < 16; d4++) {
                const float4 a = qrow[d4], bb = krow[d4];
                s += a.x * bb.x + a.y * bb.y + a.z * bb.z + a.w * bb.w;
            }
            sc[jj] = s + maskrow[t * 64 + j];
        }

        float mt = sc[0];
        #pragma unroll
        for (int jj = 1; jj < 16; jj++) mt = fmaxf(mt, sc[jj]);
        mt = fmaxf(mt, __shfl_xor_sync(0xffffffffu, mt, 1));
        mt = fmaxf(mt, __shfl_xor_sync(0xffffffffu, mt, 2));
        const float mnew  = fmaxf(mrun, mt);
        const float scale = __expf(mrun - mnew);

        float lsum = 0.f;
        #pragma unroll
        for (int jj = 0; jj < 16; jj++) { sc[jj] = __expf(sc[jj] - mnew); lsum += sc[jj]; }
        lsum += __shfl_xor_sync(0xffffffffu, lsum, 1);
        lsum += __shfl_xor_sync(0xffffffffu, lsum, 2);
        lrun = lrun * scale + lsum;
        mrun = mnew;
        #pragma unroll
        for (int dd = 0; dd < 16; dd++) acc[dd] *= scale;

        __syncthreads();
        #pragma unroll
        for (int jj = 0; jj < 16; jj++) Ps[r * 64 + d0 + jj] = sc[jj];
        __syncthreads();

        #pragma unroll
        for (int j = 0; j < 64; j++) {
            const float pv = Ps[r * 64 + j];
            const float4* vrow = (const float4*)(Vs + j * 64 + d0);
            #pragma unroll
            for (int q4 = 0; q4 < 4; q4++) {
                const float4 v = vrow[q4];
                acc[q4 * 4 + 0] += pv * v.x;
                acc[q4 * 4 + 1] += pv * v.y;
                acc[q4 * 4 + 2] += pv * v.z;
                acc[q4 * 4 + 3] += pv * v.w;
            }
        }
    }

    const float inv_l = 1.f / lrun;
    __half* orow = O + qbase + (size_t)r * HID + d0;
    #pragma unroll
    for (int dd = 0; dd < 16; dd += 4) {
        __half2 h0 = __floats2half2_rn(acc[dd] * inv_l,     acc[dd + 1] * inv_l);
        __half2 h1 = __floats2half2_rn(acc[dd + 2] * inv_l, acc[dd + 3] * inv_l);
        *(uint2*)(orow + dd) = make_uint2(*(uint32_t*)&h0, *(uint32_t*)&h1);
    }
}

// ---------------------------------------------------------------------------
// act = silu(gate) * up -> half (feeds down GEMM)
// ---------------------------------------------------------------------------
__global__ void silu_mul_k(const float* __restrict__ g, const float* __restrict__ u,
                           __half* __restrict__ a, int n4)
{
    const int i = blockIdx.x * blockDim.x + threadIdx.x;
    if (i >= n4) return;
    const float4 gv = *(const float4*)(g + (size_t)i * 4);
    const float4 uv = *(const float4*)(u + (size_t)i * 4);
    __half2 h0 = __floats2half2_rn(gv.x / (1.f + __expf(-gv.x)) * uv.x,
                                   gv.y / (1.f + __expf(-gv.y)) * uv.y);
    __half2 h1 = __floats2half2_rn(gv.z / (1.f + __expf(-gv.z)) * uv.z,
                                   gv.w / (1.f + __expf(-gv.w)) * uv.w);
    ((uint2*)a)[i] = make_uint2(*(uint32_t*)&h0, *(uint32_t*)&h1);
}

// ---------------------------------------------------------------------------
// Orchestration
// ---------------------------------------------------------------------------
static inline void half_pass(const float* src, __half* dst, size_t n)
{
    const int n4 = (int)(n / 4);
    to_half_k<<<(n4 + 255) / 256, 256>>>(src, dst, n4);
}

extern "C" void kernel_launch(void* const* d_in, const int* in_sizes, int n_in,
                              void* d_out, int out_size)
{
    const float* hid   = (const float*)d_in[0];
    const float* mem   = (const float*)d_in[1];
    const float* mask  = (const float*)d_in[2];
    const int*   pos   = (const int*)  d_in[3];
    const float* Wq    = (const float*)d_in[4];
    const float* Wk    = (const float*)d_in[5];
    const float* Wv    = (const float*)d_in[6];
    const float* Wo    = (const float*)d_in[7];
    const float* ln1w  = (const float*)d_in[8];
    const float* ln1b  = (const float*)d_in[9];
    const float* ln2w  = (const float*)d_in[10];
    const float* ln2b  = (const float*)d_in[11];
    const float* gatew = (const float*)d_in[12];
    const float* upw   = (const float*)d_in[13];
    const float* downw = (const float*)d_in[14];
    float* out = (float*)d_out;

    float *q, *k, *v, *h, *gg, *uu;
    __half *xlnh, *memh, *ctxh, *yh, *acth;
    __half *wq, *wk, *wv, *wo, *gw, *uw, *dw;
    cudaGetSymbolAddress((void**)&q,    g_q);
    cudaGetSymbolAddress((void**)&k,    g_k);
    cudaGetSymbolAddress((void**)&v,    g_v);
    cudaGetSymbolAddress((void**)&h,    g_h);
    cudaGetSymbolAddress((void**)&gg,   g_gate);
    cudaGetSymbolAddress((void**)&uu,   g_up);
    cudaGetSymbolAddress((void**)&xlnh, g_xln_h);
    cudaGetSymbolAddress((void**)&memh, g_mem_h);
    cudaGetSymbolAddress((void**)&ctxh, g_ctx_h);
    cudaGetSymbolAddress((void**)&yh,   g_y_h);
    cudaGetSymbolAddress((void**)&acth, g_act_h);
    cudaGetSymbolAddress((void**)&wq,   g_wq);
    cudaGetSymbolAddress((void**)&wk,   g_wk);
    cudaGetSymbolAddress((void**)&wv,   g_wv);
    cudaGetSymbolAddress((void**)&wo,   g_wo);
    cudaGetSymbolAddress((void**)&gw,   g_gw);
    cudaGetSymbolAddress((void**)&uw,   g_uw);
    cudaGetSymbolAddress((void**)&dw,   g_dw);

    cudaFuncSetAttribute(gemm_mma, cudaFuncAttributeMaxDynamicSharedMemorySize, GEMM_SMEM);

    // f16 conversions: weights + memory activation
    half_pass(Wq, wq, (size_t)HID * HID);
    half_pass(Wk, wk, (size_t)HID * HID);
    half_pass(Wv, wv, (size_t)HID * HID);
    half_pass(Wo, wo, (size_t)HID * HID);
    half_pass(gatew, gw, (size_t)DFF * HID);
    half_pass(upw,   uw, (size_t)DFF * HID);
    half_pass(downw, dw, (size_t)HID * DFF);
    half_pass(mem, memh, (size_t)NTOK * HID);

    // 1. ln1 -> half
    layernorm_k<<<NTOK, 256>>>(hid, ln1w, ln1b, xlnh);

    // 2-4. Q/K/V projections (fp16 tensor-core GEMMs, fp32 out)
    dim3 gsq(HID / GN, NTOK / GM);
    gemm_mma<<<gsq, 256, GEMM_SMEM>>>(xlnh, wq, nullptr, q, NTOK, HID, HID);
    gemm_mma<<<gsq, 256, GEMM_SMEM>>>(memh, wk, nullptr, k, NTOK, HID, HID);
    gemm_mma<<<gsq, 256, GEMM_SMEM>>>(memh, wv, nullptr, v, NTOK, HID, HID);

    // 5. RoPE (in place, fp32)
    const int rope_threads = NTOK * NHEAD * 8;
    rope_k<<<(rope_threads + 255) / 256, 256>>>(q, k, pos);

    // 6. Attention -> ctx (half)
    dim3 ga(SEQ / 64, NHEAD, BATCH);
    attn_k<<<ga, 256>>>(q, k, v, mask, ctxh);

    // 7. O projection + residual -> h (fp32)
    gemm_mma<<<gsq, 256, GEMM_SMEM>>>(ctxh, wo, hid, h, NTOK, HID, HID);

    // 8. ln2 -> half
    layernorm_k<<<NTOK, 256>>>(h, ln2w, ln2b, yh);

    // 9-10. gate / up (fp32 out)
    dim3 gff(DFF / GN, NTOK / GM);
    gemm_mma<<<gff, 256, GEMM_SMEM>>>(yh, gw, nullptr, gg, NTOK, DFF, HID);
    gemm_mma<<<gff, 256, GEMM_SMEM>>>(yh, uw, nullptr, uu, NTOK, DFF, HID);

    // 11. silu(gate) * up -> half
    const int n4 = (NTOK * DFF) / 4;
    silu_mul_k<<<(n4 + 255) / 256, 256>>>(gg, uu, acth, n4);

    // 12. down projection + residual -> out (fp32)
    gemm_mma<<<gsq, 256, GEMM_SMEM>>>(acth, dw, h, out, NTOK, HID, DFF);
}

// round 16
// speedup vs baseline: 3.8855x; 3.0786x over previous
#include <cuda_runtime.h>
#include <cuda_fp16.h>
#include <cstdint>
#include <math.h>

// ---------------------------------------------------------------------------
// Problem constants
// ---------------------------------------------------------------------------
#define HID   2048
#define NHEAD 32
#define HDIM  64
#define DFF   8192
#define SEQ   1024
#define BATCH 2
#define NTOK  (BATCH * SEQ)          // 2048 tokens

// ---------------------------------------------------------------------------
// Scratch (device globals; no allocations allowed)
// ---------------------------------------------------------------------------
__device__ float  g_q   [NTOK * HID];
__device__ float  g_k   [NTOK * HID];
__device__ float  g_v   [NTOK * HID];
__device__ float  g_h   [NTOK * HID];
__device__ float  g_gate[(size_t)NTOK * DFF];
__device__ float  g_up  [(size_t)NTOK * DFF];
// half activations
__device__ __half g_xln_h[NTOK * HID];
__device__ __half g_mem_h[NTOK * HID];
__device__ __half g_ctx_h[NTOK * HID];
__device__ __half g_y_h  [NTOK * HID];
__device__ __half g_act_h[(size_t)NTOK * DFF];
__device__ __half g_qh  [NTOK * HID];
__device__ __half g_kh  [NTOK * HID];
__device__ __half g_vh  [NTOK * HID];
// half weights
__device__ __half g_wq [HID * HID];
__device__ __half g_wk [HID * HID];
__device__ __half g_wv [HID * HID];
__device__ __half g_wo [HID * HID];
__device__ __half g_gw [(size_t)DFF * HID];
__device__ __half g_uw [(size_t)DFF * HID];
__device__ __half g_dw [(size_t)HID * DFF];

// ---------------------------------------------------------------------------
// Helpers
// ---------------------------------------------------------------------------
__device__ __forceinline__ uint32_t smem_u32(const void* p) {
    uint32_t a;
    asm("{ .reg .u64 t; cvta.to.shared.u64 t, %1; cvt.u32.u64 %0, t; }"
        : "=r"(a) : "l"(p));
    return a;
}

__device__ __forceinline__ void cp16(uint32_t s, const void* g) {
    asm volatile("cp.async.cg.shared.global [%0], [%1], 16;" :: "r"(s), "l"(g));
}
#define CP_COMMIT() asm volatile("cp.async.commit_group;" ::: "memory")
#define CP_WAIT2()  asm volatile("cp.async.wait_group 2;" ::: "memory")
#define CP_WAIT0()  asm volatile("cp.async.wait_group 0;" ::: "memory")

// fp16 tensor-core mma, fp32 accumulate (sm_80+ PTX, family-target safe)
__device__ __forceinline__ void mma_f16(float* c, const uint32_t* a, const uint32_t* b) {
    asm volatile(
        "mma.sync.aligned.m16n8k16.row.col.f32.f16.f16.f32 "
        "{%0,%1,%2,%3}, {%4,%5,%6,%7}, {%8,%9}, {%0,%1,%2,%3};"
        : "+f"(c[0]), "+f"(c[1]), "+f"(c[2]), "+f"(c[3])
        : "r"(a[0]), "r"(a[1]), "r"(a[2]), "r"(a[3]), "r"(b[0]), "r"(b[1]));
}

__device__ __forceinline__ void ldsm_x4(uint32_t* r, uint32_t addr) {
    asm volatile("ldmatrix.sync.aligned.m8n8.x4.shared.b16 {%0,%1,%2,%3}, [%4];"
        : "=r"(r[0]), "=r"(r[1]), "=r"(r[2]), "=r"(r[3]) : "r"(addr));
}

__device__ __forceinline__ void ldsm_x4_t(uint32_t* r, uint32_t addr) {
    asm volatile("ldmatrix.sync.aligned.m8n8.x4.trans.shared.b16 {%0,%1,%2,%3}, [%4];"
        : "=r"(r[0]), "=r"(r[1]), "=r"(r[2]), "=r"(r[3]) : "r"(addr));
}

__device__ __forceinline__ uint32_t packh2(float a, float b) {
    __half2 h = __floats2half2_rn(a, b);
    return *(uint32_t*)&h;
}

// ---------------------------------------------------------------------------
// f32 -> f16 conversion pass
// ---------------------------------------------------------------------------
__global__ void to_half_k(const float* __restrict__ x, __half* __restrict__ y, int n4)
{
    const int i = blockIdx.x * blockDim.x + threadIdx.x;
    if (i >= n4) return;
    const float4 v = ((const float4*)x)[i];
    __half2 h0 = __floats2half2_rn(v.x, v.y);
    __half2 h1 = __floats2half2_rn(v.z, v.w);
    ((uint2*)y)[i] = make_uint2(*(uint32_t*)&h0, *(uint32_t*)&h1);
}

// ---------------------------------------------------------------------------
// LayerNorm: one block per row; writes half
// ---------------------------------------------------------------------------
__global__ __launch_bounds__(256) void layernorm_k(
    const float* __restrict__ X, const float* __restrict__ w,
    const float* __restrict__ b, __half* __restrict__ Y)
{
    const int row = blockIdx.x;
    const float* x = X + (size_t)row * HID;
    float sum = 0.f, sq = 0.f;
    for (int c = threadIdx.x * 4; c < HID; c += 256 * 4) {
        float4 v = *(const float4*)(x + c);
        sum += v.x + v.y + v.z + v.w;
        sq  += v.x * v.x + v.y * v.y + v.z * v.z + v.w * v.w;
    }
    __shared__ float s1[8], s2[8];
    #pragma unroll
    for (int o = 16; o > 0; o >>= 1) {
        sum += __shfl_xor_sync(0xffffffffu, sum, o);
        sq  += __shfl_xor_sync(0xffffffffu, sq, o);
    }
    if ((threadIdx.x & 31) == 0) { s1[threadIdx.x >> 5] = sum; s2[threadIdx.x >> 5] = sq; }
    __syncthreads();
    if (threadIdx.x < 32) {
        sum = (threadIdx.x < 8) ? s1[threadIdx.x] : 0.f;
        sq  = (threadIdx.x < 8) ? s2[threadIdx.x] : 0.f;
        #pragma unroll
        for (int o = 4; o > 0; o >>= 1) {
            sum += __shfl_xor_sync(0xffffffffu, sum, o);
            sq  += __shfl_xor_sync(0xffffffffu, sq, o);
        }
        if (threadIdx.x == 0) { s1[0] = sum; s2[0] = sq; }
    }
    __syncthreads();
    const float mean = s1[0] * (1.f / HID);
    const float var  = s2[0] * (1.f / HID) - mean * mean;
    const float rstd = rsqrtf(var + 1e-5f);
    __half* y = Y + (size_t)row * HID;
    for (int c = threadIdx.x * 4; c < HID; c += 256 * 4) {
        float4 v  = *(const float4*)(x + c);
        float4 wv = *(const float4*)(w + c);
        float4 bv = *(const float4*)(b + c);
        __half2 h0 = __floats2half2_rn((v.x - mean) * rstd * wv.x + bv.x,
                                       (v.y - mean) * rstd * wv.y + bv.y);
        __half2 h1 = __floats2half2_rn((v.z - mean) * rstd * wv.z + bv.z,
                                       (v.w - mean) * rstd * wv.w + bv.w);
        *(uint2*)(y + c) = make_uint2(*(uint32_t*)&h0, *(uint32_t*)&h1);
    }
}

// ---------------------------------------------------------------------------
// FP16 tensor-core NT GEMM (proven R14; redundant loop-end sync removed)
// ---------------------------------------------------------------------------
#define GM 128
#define GN 256
#define BKH 32
#define LDH 40
#define A_STG (GM * LDH)
#define B_STG (GN * LDH)
#define NSTAGE 4
#define GEMM_SMEM (NSTAGE * (A_STG + B_STG) * 2)   // 122880 bytes

__device__ __forceinline__ void load_stage_h(
    int tid, const __half* Ag, const __half* Bg, int K, int k0,
    uint32_t sA, uint32_t sB)
{
    #pragma unroll
    for (int t = 0; t < 2; t++) {
        const int idx = tid + t * 256;
        const int row = idx >> 2, c = idx & 3;
        cp16(sA + (uint32_t)(row * LDH + c * 8) * 2, Ag + (size_t)row * K + k0 + c * 8);
    }
    #pragma unroll
    for (int t = 0; t < 4; t++) {
        const int idx = tid + t * 256;
        const int row = idx >> 2, c = idx & 3;
        cp16(sB + (uint32_t)(row * LDH + c * 8) * 2, Bg + (size_t)row * K + k0 + c * 8);
    }
}

__global__ __launch_bounds__(256, 1) void gemm_mma(
    const __half* __restrict__ A, const __half* __restrict__ B,
    const float* __restrict__ Cin, float* __restrict__ C,
    int M, int N, int K)
{
    extern __shared__ __half hsm[];
    __half* smA = hsm;
    __half* smB = hsm + NSTAGE * A_STG;

    const int tid  = threadIdx.x;
    const int wid  = tid >> 5;
    const int lane = tid & 31;
    const int wm   = wid & 1;
    const int wn   = wid >> 1;
    const int m0   = blockIdx.y * GM;
    const int n0   = blockIdx.x * GN;

    const __half* Ag = A + (size_t)m0 * K;
    const __half* Bg = B + (size_t)n0 * K;

    const uint32_t sAu = smem_u32(smA);
    const uint32_t sBu = smem_u32(smB);

    const int rowA = wm * 64 + (lane & 7) + 8 * ((lane >> 3) & 1);
    const int kA   = 8 * (lane >> 4);
    const int rowB = wn * 64 + (lane & 7) + 8 * (lane >> 4);
    const int kB   = 8 * ((lane >> 3) & 1);

    float acc[4][8][4] = {};

    const int S = K / BKH;

    #pragma unroll
    for (int p = 0; p < 3; p++) {
        load_stage_h(tid, Ag, Bg, K, p * BKH,
                     sAu + (uint32_t)(p * A_STG) * 2, sBu + (uint32_t)(p * B_STG) * 2);
        CP_COMMIT();
    }

    for (int s = 0; s < S; s++) {
        const int b = s & (NSTAGE - 1);
        CP_WAIT2();
        __syncthreads();

        if (s + 3 < S) {
            const int nb = (s + 3) & (NSTAGE - 1);
            load_stage_h(tid, Ag, Bg, K, (s + 3) * BKH,
                         sAu + (uint32_t)(nb * A_STG) * 2, sBu + (uint32_t)(nb * B_STG) * 2);
        }
        CP_COMMIT();

        const uint32_t aBase = sAu + (uint32_t)(b * A_STG) * 2;
        const uint32_t bBase = sBu + (uint32_t)(b * B_STG) * 2;

        #pragma unroll
        for (int ks = 0; ks < 2; ks++) {
            const int k0 = ks * 16;
            uint32_t af[4][4];
            #pragma unroll
            for (int mf = 0; mf < 4; mf++)
                ldsm_x4(af[mf], aBase + (uint32_t)((rowA + mf * 16) * LDH + k0 + kA) * 2);
            uint32_t bf[4][4];
            #pragma unroll
            for (int np = 0; np < 4; np++)
                ldsm_x4(bf[np], bBase + (uint32_t)((rowB + np * 16) * LDH + k0 + kB) * 2);
            #pragma unroll
            for (int mf = 0; mf < 4; mf++)
                #pragma unroll
                for (int nf = 0; nf < 8; nf++)
                    mma_f16(acc[mf][nf], af[mf], bf[nf >> 1] + 2 * (nf & 1));
        }
        __syncthreads();   // reads of stage b done before next iter's store issue
    }

    const int lr = lane >> 2;
    const int lc = lane & 3;
    #pragma unroll
    for (int mf = 0; mf < 4; mf++) {
        const int r0 = m0 + wm * 64 + mf * 16 + lr;
        #pragma unroll
        for (int nf = 0; nf < 8; nf++) {
            const int c0 = n0 + wn * 64 + nf * 8 + 2 * lc;
            float2 v0 = make_float2(acc[mf][nf][0], acc[mf][nf][1]);
            float2 v1 = make_float2(acc[mf][nf][2], acc[mf][nf][3]);
            if (Cin) {
                const float2 p0 = *(const float2*)(Cin + (size_t)r0 * N + c0);
                const float2 p1 = *(const float2*)(Cin + (size_t)(r0 + 8) * N + c0);
                v0.x += p0.x; v0.y += p0.y;
                v1.x += p1.x; v1.y += p1.y;
            }
            *(float2*)(C + (size_t)r0 * N + c0)       = v0;
            *(float2*)(C + (size_t)(r0 + 8) * N + c0) = v1;
        }
    }
}

// ---------------------------------------------------------------------------
// RoPE + convert: fp32 q,k,v -> half qh,kh,vh. q pre-scaled by 1/8.
// One thread per (token, head).
// ---------------------------------------------------------------------------
__global__ __launch_bounds__(256) void rope_half_k(
    const float* __restrict__ q, const float* __restrict__ k,
    const float* __restrict__ v, const int* __restrict__ pos_ids,
    __half* __restrict__ qh, __half* __restrict__ kh, __half* __restrict__ vh)
{
    const int idx = blockIdx.x * blockDim.x + threadIdx.x;
    if (idx >= NTOK * NHEAD) return;
    const int tkn = idx >> 5;
    const int h   = idx & 31;
    const size_t base = (size_t)tkn * HID + h * HDIM;
    const float pos = (float)pos_ids[tkn];

    float cs[8], sn[8];
    #pragma unroll
    for (int d = 0; d < 8; d++) {
        const float inv = powf(10000.f, -(float)d * 0.125f);
        sincosf(pos * inv, &sn[d], &cs[d]);
    }

    // q: rope dims 0..15, scale all by 0.125
    {
        float x[16];
        #pragma unroll
        for (int c = 0; c < 16; c += 4) *(float4*)(x + c) = *(const float4*)(q + base + c);
        float o[16];
        #pragma unroll
        for (int d = 0; d < 8; d++) {
            o[d]     = x[d] * cs[d] - x[d + 8] * sn[d];
            o[d + 8] = x[d + 8] * cs[d] + x[d] * sn[d];
        }
        #pragma unroll
        for (int c = 0; c < 16; c += 2)
            *(uint32_t*)(qh + base + c) = packh2(o[c] * 0.125f, o[c + 1] * 0.125f);
        #pragma unroll
        for (int c = 16; c < 64; c += 4) {
            const float4 p = *(const float4*)(q + base + c);
            *(uint32_t*)(qh + base + c)     = packh2(p.x * 0.125f, p.y * 0.125f);
            *(uint32_t*)(qh + base + c + 2) = packh2(p.z * 0.125f, p.w * 0.125f);
        }
    }
    // k: rope dims 0..15
    {
        float x[16];
        #pragma unroll
        for (int c = 0; c < 16; c += 4) *(float4*)(x + c) = *(const float4*)(k + base + c);
        float o[16];
        #pragma unroll
        for (int d = 0; d < 8; d++) {
            o[d]     = x[d] * cs[d] - x[d + 8] * sn[d];
            o[d + 8] = x[d + 8] * cs[d] + x[d] * sn[d];
        }
        #pragma unroll
        for (int c = 0; c < 16; c += 2)
            *(uint32_t*)(kh + base + c) = packh2(o[c], o[c + 1]);
        #pragma unroll
        for (int c = 16; c < 64; c += 4) {
            const float4 p = *(const float4*)(k + base + c);
            *(uint32_t*)(kh + base + c)     = packh2(p.x, p.y);
            *(uint32_t*)(kh + base + c + 2) = packh2(p.z, p.w);
        }
    }
    // v: plain convert
    #pragma unroll
    for (int c = 0; c < 64; c += 4) {
        const float4 p = *(const float4*)(v + base + c);
        *(uint32_t*)(vh + base + c)     = packh2(p.x, p.y);
        *(uint32_t*)(vh + base + c + 2) = packh2(p.z, p.w);
    }
}

// ---------------------------------------------------------------------------
// Tensor-core flash attention: grid (SEQ/64, NHEAD, BATCH), 128 threads.
// 4 warps x 16 q-rows. QK^T and PV via m16n8k16, fp32 accum, online softmax.
// ---------------------------------------------------------------------------
#define LDK 72   // smem row stride in halves for K/V tiles

__global__ __launch_bounds__(128) void attn_mma(
    const __half* __restrict__ Qh, const __half* __restrict__ Kh,
    const __half* __restrict__ Vh, const float* __restrict__ mask,
    __half* __restrict__ O)
{
    __shared__ __half Ks[64 * LDK];
    __shared__ __half Vs[64 * LDK];

    const int qt = blockIdx.x, h = blockIdx.y, b = blockIdx.z;
    const int tid  = threadIdx.x;
    const int wid  = tid >> 5;
    const int lane = tid & 31;
    const int lr   = lane >> 2;
    const int lc   = lane & 3;

    const uint32_t sK = smem_u32(Ks);
    const uint32_t sV = smem_u32(Vs);

    // ldmatrix lane addressing
    const int rowBk = (lane & 7) + 8 * (lane >> 4);         // K (non-trans): n=kv rows
    const int kBk   = 8 * ((lane >> 3) & 1);                //               k=d offset
    const int rowV  = (lane & 7) + 8 * ((lane >> 3) & 1);   // V (trans): kv rows
    const int colV  = 8 * (lane >> 4);                      //            d offset

    const int tb = b * SEQ + qt * 64;        // first token of Q tile
    const int qrow = wid * 16 + lr;          // within tile

    // Q a-fragments (held whole block): aQ[t][4] for d chunks t
    uint32_t aQ[4][4];
    {
        const __half* qp = Qh + (size_t)(tb + qrow) * HID + h * HDIM;
        #pragma unroll
        for (int t = 0; t < 4; t++) {
            const __half* p = qp + t * 16 + 2 * lc;
            aQ[t][0] = *(const uint32_t*)(p);
            aQ[t][1] = *(const uint32_t*)(p + 8 * HID);
            aQ[t][2] = *(const uint32_t*)(p + 8);
            aQ[t][3] = *(const uint32_t*)(p + 8 * HID + 8);
        }
    }

    float oacc[8][4] = {};
    float m0 = -1e30f, m1 = -1e30f, l0 = 0.f, l1 = 0.f;

    const float* mrow0 = mask + ((size_t)b * SEQ + qt * 64 + qrow) * SEQ;
    const float* mrow1 = mrow0 + 8 * SEQ;

    for (int t = 0; t < SEQ / 64; t++) {
        __syncthreads();                       // prior tile reads complete
        // load K/V 64x64 tiles
        {
            const __half* kg = Kh + (size_t)(b * SEQ + t * 64) * HID + h * HDIM;
            const __half* vg = Vh + (size_t)(b * SEQ + t * 64) * HID + h * HDIM;
            #pragma unroll
            for (int i = 0; i < 4; i++) {
                const int idx = tid + i * 128;
                const int row = idx >> 3, c = idx & 7;
                cp16(sK + (uint32_t)(row * LDK + c * 8) * 2, kg + (size_t)row * HID + c * 8);
                cp16(sV + (uint32_t)(row * LDK + c * 8) * 2, vg + (size_t)row * HID + c * 8);
            }
        }
        CP_COMMIT();
        CP_WAIT0();
        __syncthreads();

        // scores: S[16 x 64] per warp
        float sc[8][4] = {};
        #pragma unroll
        for (int kd = 0; kd < 4; kd++) {
            uint32_t bfK[4][4];
            #pragma unroll
            for (int np = 0; np < 4; np++)
                ldsm_x4(bfK[np], sK + (uint32_t)((np * 16 + rowBk) * LDK + kd * 16 + kBk) * 2);
            #pragma unroll
            for (int nf = 0; nf < 8; nf++)
                mma_f16(sc[nf], aQ[kd], bfK[nf >> 1] + 2 * (nf & 1));
        }

        // + mask
        const int c0base = t * 64 + 2 * lc;
        #pragma unroll
        for (int nf = 0; nf < 8; nf++) {
            const int c0 = c0base + 8 * nf;
            sc[nf][0] += mrow0[c0];     sc[nf][1] += mrow0[c0 + 1];
            sc[nf][2] += mrow1[c0];     sc[nf][3] += mrow1[c0 + 1];
        }

        // row maxima
        float mt0 = -1e30f, mt1 = -1e30f;
        #pragma unroll
        for (int nf = 0; nf < 8; nf++) {
            mt0 = fmaxf(mt0, fmaxf(sc[nf][0], sc[nf][1]));
            mt1 = fmaxf(mt1, fmaxf(sc[nf][2], sc[nf][3]));
        }
        mt0 = fmaxf(mt0, __shfl_xor_sync(0xffffffffu, mt0, 1));
        mt0 = fmaxf(mt0, __shfl_xor_sync(0xffffffffu, mt0, 2));
        mt1 = fmaxf(mt1, __shfl_xor_sync(0xffffffffu, mt1, 1));
        mt1 = fmaxf(mt1, __shfl_xor_sync(0xffffffffu, mt1, 2));
        const float mn0 = fmaxf(m0, mt0), mn1 = fmaxf(m1, mt1);
        const float al0 = __expf(m0 - mn0), al1 = __expf(m1 - mn1);

        float ls0 = 0.f, ls1 = 0.f;
        #pragma unroll
        for (int nf = 0; nf < 8; nf++) {
            sc[nf][0] = __expf(sc[nf][0] - mn0); ls0 += sc[nf][0];
            sc[nf][1] = __expf(sc[nf][1] - mn0); ls0 += sc[nf][1];
            sc[nf][2] = __expf(sc[nf][2] - mn1); ls1 += sc[nf][2];
            sc[nf][3] = __expf(sc[nf][3] - mn1); ls1 += sc[nf][3];
        }
        ls0 += __shfl_xor_sync(0xffffffffu, ls0, 1);
        ls0 += __shfl_xor_sync(0xffffffffu, ls0, 2);
        ls1 += __shfl_xor_sync(0xffffffffu, ls1, 1);
        ls1 += __shfl_xor_sync(0xffffffffu, ls1, 2);
        l0 = l0 * al0 + ls0;  l1 = l1 * al1 + ls1;
        m0 = mn0;  m1 = mn1;

        #pragma unroll
        for (int nf = 0; nf < 8; nf++) {
            oacc[nf][0] *= al0; oacc[nf][1] *= al0;
            oacc[nf][2] *= al1; oacc[nf][3] *= al1;
        }

        // pack P into A fragments: aP[j] covers kv chunk 16j..16j+15
        uint32_t aP[4][4];
        #pragma unroll
        for (int j = 0; j < 4; j++) {
            aP[j][0] = packh2(sc[2 * j][0],     sc[2 * j][1]);
            aP[j][1] = packh2(sc[2 * j][2],     sc[2 * j][3]);
            aP[j][2] = packh2(sc[2 * j + 1][0], sc[2 * j + 1][1]);
            aP[j][3] = packh2(sc[2 * j + 1][2], sc[2 * j + 1][3]);
        }

        // O += P @ V
        #pragma unroll
        for (int j = 0; j < 4; j++) {
            uint32_t bfV[4][4];
            #pragma unroll
            for (int np = 0; np < 4; np++)
                ldsm_x4_t(bfV[np], sV + (uint32_t)((16 * j + rowV) * LDK + 16 * np + colV) * 2);
            #pragma unroll
            for (int nf = 0; nf < 8; nf++)
                mma_f16(oacc[nf], aP[j], bfV[nf >> 1] + 2 * (nf & 1));
        }
    }

    const float i0 = 1.f / l0, i1 = 1.f / l1;
    __half* o0 = O + (size_t)(tb + qrow) * HID + h * HDIM + 2 * lc;
    __half* o1 = o0 + 8 * HID;
    #pragma unroll
    for (int nf = 0; nf < 8; nf++) {
        *(uint32_t*)(o0 + 8 * nf) = packh2(oacc[nf][0] * i0, oacc[nf][1] * i0);
        *(uint32_t*)(o1 + 8 * nf) = packh2(oacc[nf][2] * i1, oacc[nf][3] * i1);
    }
}

// ---------------------------------------------------------------------------
// act = silu(gate) * up -> half
// ---------------------------------------------------------------------------
__global__ void silu_mul_k(const float* __restrict__ g, const float* __restrict__ u,
                           __half* __restrict__ a, int n4)
{
    const int i = blockIdx.x * blockDim.x + threadIdx.x;
    if (i >= n4) return;
    const float4 gv = *(const float4*)(g + (size_t)i * 4);
    const float4 uv = *(const float4*)(u + (size_t)i * 4);
    __half2 h0 = __floats2half2_rn(gv.x / (1.f + __expf(-gv.x)) * uv.x,
                                   gv.y / (1.f + __expf(-gv.y)) * uv.y);
    __half2 h1 = __floats2half2_rn(gv.z / (1.f + __expf(-gv.z)) * uv.z,
                                   gv.w / (1.f + __expf(-gv.w)) * uv.w);
    ((uint2*)a)[i] = make_uint2(*(uint32_t*)&h0, *(uint32_t*)&h1);
}

// ---------------------------------------------------------------------------
// Orchestration
// ---------------------------------------------------------------------------
static inline void half_pass(const float* src, __half* dst, size_t n)
{
    const int n4 = (int)(n / 4);
    to_half_k<<<(n4 + 255) / 256, 256>>>(src, dst, n4);
}

extern "C" void kernel_launch(void* const* d_in, const int* in_sizes, int n_in,
                              void* d_out, int out_size)
{
    const float* hid   = (const float*)d_in[0];
    const float* mem   = (const float*)d_in[1];
    const float* mask  = (const float*)d_in[2];
    const int*   pos   = (const int*)  d_in[3];
    const float* Wq    = (const float*)d_in[4];
    const float* Wk    = (const float*)d_in[5];
    const float* Wv    = (const float*)d_in[6];
    const float* Wo    = (const float*)d_in[7];
    const float* ln1w  = (const float*)d_in[8];
    const float* ln1b  = (const float*)d_in[9];
    const float* ln2w  = (const float*)d_in[10];
    const float* ln2b  = (const float*)d_in[11];
    const float* gatew = (const float*)d_in[12];
    const float* upw   = (const float*)d_in[13];
    const float* downw = (const float*)d_in[14];
    float* out = (float*)d_out;

    float *q, *k, *v, *h, *gg, *uu;
    __half *xlnh, *memh, *ctxh, *yh, *acth, *qh, *kh, *vh;
    __half *wq, *wk, *wv, *wo, *gw, *uw, *dw;
    cudaGetSymbolAddress((void**)&q,    g_q);
    cudaGetSymbolAddress((void**)&k,    g_k);
    cudaGetSymbolAddress((void**)&v,    g_v);
    cudaGetSymbolAddress((void**)&h,    g_h);
    cudaGetSymbolAddress((void**)&gg,   g_gate);
    cudaGetSymbolAddress((void**)&uu,   g_up);
    cudaGetSymbolAddress((void**)&xlnh, g_xln_h);
    cudaGetSymbolAddress((void**)&memh, g_mem_h);
    cudaGetSymbolAddress((void**)&ctxh, g_ctx_h);
    cudaGetSymbolAddress((void**)&yh,   g_y_h);
    cudaGetSymbolAddress((void**)&acth, g_act_h);
    cudaGetSymbolAddress((void**)&qh,   g_qh);
    cudaGetSymbolAddress((void**)&kh,   g_kh);
    cudaGetSymbolAddress((void**)&vh,   g_vh);
    cudaGetSymbolAddress((void**)&wq,   g_wq);
    cudaGetSymbolAddress((void**)&wk,   g_wk);
    cudaGetSymbolAddress((void**)&wv,   g_wv);
    cudaGetSymbolAddress((void**)&wo,   g_wo);
    cudaGetSymbolAddress((void**)&gw,   g_gw);
    cudaGetSymbolAddress((void**)&uw,   g_uw);
    cudaGetSymbolAddress((void**)&dw,   g_dw);

    cudaFuncSetAttribute(gemm_mma, cudaFuncAttributeMaxDynamicSharedMemorySize, GEMM_SMEM);

    // f16 conversions: weights + memory activation
    half_pass(Wq, wq, (size_t)HID * HID);
    half_pass(Wk, wk, (size_t)HID * HID);
    half_pass(Wv, wv, (size_t)HID * HID);
    half_pass(Wo, wo, (size_t)HID * HID);
    half_pass(gatew, gw, (size_t)DFF * HID);
    half_pass(upw,   uw, (size_t)DFF * HID);
    half_pass(downw, dw, (size_t)HID * DFF);
    half_pass(mem, memh, (size_t)NTOK * HID);

    // 1. ln1 -> half
    layernorm_k<<<NTOK, 256>>>(hid, ln1w, ln1b, xlnh);

    // 2-4. Q/K/V projections
    dim3 gsq(HID / GN, NTOK / GM);
    gemm_mma<<<gsq, 256, GEMM_SMEM>>>(xlnh, wq, nullptr, q, NTOK, HID, HID);
    gemm_mma<<<gsq, 256, GEMM_SMEM>>>(memh, wk, nullptr, k, NTOK, HID, HID);
    gemm_mma<<<gsq, 256, GEMM_SMEM>>>(memh, wv, nullptr, v, NTOK, HID, HID);

    // 5. RoPE + convert to half (q scaled by 1/8)
    rope_half_k<<<(NTOK * NHEAD + 255) / 256, 256>>>(q, k, v, pos, qh, kh, vh);

    // 6. Tensor-core attention -> ctx (half)
    dim3 ga(SEQ / 64, NHEAD, BATCH);
    attn_mma<<<ga, 128>>>(qh, kh, vh, mask, ctxh);

    // 7. O projection + residual -> h (fp32)
    gemm_mma<<<gsq, 256, GEMM_SMEM>>>(ctxh, wo, hid, h, NTOK, HID, HID);

    // 8. ln2 -> half
    layernorm_k<<<NTOK, 256>>>(h, ln2w, ln2b, yh);

    // 9-10. gate / up
    dim3 gff(DFF / GN, NTOK / GM);
    gemm_mma<<<gff, 256, GEMM_SMEM>>>(yh, gw, nullptr, gg, NTOK, DFF, HID);
    gemm_mma<<<gff, 256, GEMM_SMEM>>>(yh, uw, nullptr, uu, NTOK, DFF, HID);

    // 11. silu(gate) * up -> half
    const int n4 = (NTOK * DFF) / 4;
    silu_mul_k<<<(n4 + 255) / 256, 256>>>(gg, uu, acth, n4);

    // 12. down projection + residual -> out (fp32)
    gemm_mma<<<gsq, 256, GEMM_SMEM>>>(acth, dw, h, out, NTOK, HID, DFF);
}